// round 11
// baseline (speedup 1.0000x reference)
#include <cuda_runtime.h>
#include <cstdint>
#include <math.h>

#define BATCH 2
#define NH    12
#define HD    64
#define DIM   768
#define QT    8
#define QHH   14
#define QW    14
#define SEQ   1568
#define KSEQ  1600
#define MROWS 3136
#define LOG2E 1.44269504f

// ---------------- scratch ------------------------------------------------------
__device__ float g_qh[BATCH*NH*KSEQ*HD];    // [bn][k][c]
__device__ float g_kh[BATCH*NH*KSEQ*HD];    // [bn][k][c]  (pad rows stay 0)
__device__ float g_vt[BATCH*NH*HD*KSEQ];    // [bn][c][k]  (pad cols stay 0)
__device__ float g_attn[MROWS*DIM];
// pre-rounded (tf32-RNA) copies
__device__ float g_wq[DIM*DIM];
__device__ float g_wk[DIM*DIM];
__device__ float g_wv[DIM*DIM];
__device__ float g_wo[DIM*DIM];
__device__ float g_qr[MROWS*DIM];
__device__ float g_kr[MROWS*DIM];

// ---------------- helpers ------------------------------------------------------
__device__ __forceinline__ uint32_t f2tf32(float x) {
    uint32_t r;
    asm("cvt.rna.tf32.f32 %0, %1;" : "=r"(r) : "f"(x));
    return r;
}
__device__ __forceinline__ float ex2(float x) {
    float r;
    asm("ex2.approx.ftz.f32 %0, %1;" : "=f"(r) : "f"(x));
    return r;
}
__device__ __forceinline__ void mma_tf32(float* c, const uint32_t* a, const uint32_t* b) {
    asm volatile(
        "mma.sync.aligned.m16n8k8.row.col.f32.tf32.tf32.f32 "
        "{%0,%1,%2,%3}, {%4,%5,%6,%7}, {%8,%9}, {%0,%1,%2,%3};"
        : "+f"(c[0]), "+f"(c[1]), "+f"(c[2]), "+f"(c[3])
        : "r"(a[0]), "r"(a[1]), "r"(a[2]), "r"(a[3]), "r"(b[0]), "r"(b[1]));
}
__device__ __forceinline__ uint32_t smem_u32(const void* p) {
    uint32_t a;
    asm("{ .reg .u64 t; cvta.to.shared.u64 t, %1; cvt.u32.u64 %0, t; }" : "=r"(a) : "l"(p));
    return a;
}
#define CP16(dst, src) \
    asm volatile("cp.async.cg.shared.global [%0], [%1], 16;" :: "r"(dst), "l"(src))
#define CP_COMMIT() asm volatile("cp.async.commit_group;" ::: "memory")
#define CP_WAIT0()  asm volatile("cp.async.wait_group 0;" ::: "memory")
#define CP_WAIT1()  asm volatile("cp.async.wait_group 1;" ::: "memory")

__device__ __forceinline__ uint16_t pack_idx(int gk) {
    int gq = gk < SEQ ? gk : SEQ - 1;
    int kt = gq / (QHH * QW);
    int rem = gq - kt * (QHH * QW);
    int khh = rem / QW;
    int kww = rem - khh * QW;
    return (uint16_t)(kt | (khh << 3) | (kww << 7));
}

// ---------------- tf32-RNA rounding prepass ------------------------------------
__global__ __launch_bounds__(256)
void round_pass(const float* __restrict__ src, float* __restrict__ dst, int n4)
{
    int i = blockIdx.x * 256 + threadIdx.x;
    if (i < n4) {
        float4 v = ((const float4*)src)[i];
        uint4 u = make_uint4(f2tf32(v.x), f2tf32(v.y), f2tf32(v.z), f2tf32(v.w));
        ((uint4*)dst)[i] = u;
    }
}

// ---------------- tf32 mma GEMM body: cp.async staged, pre-rounded inputs -----
#define KC 32
#define LDT 36
#define STAGE_W (128 * LDT)            // words per matrix per stage
#define EPI_PITCH 132
#define GEMM_SMEM (4 * STAGE_W * 4)    // 73728 B (>= epilogue 67584)

__device__ __forceinline__
void gemm_body(const float* __restrict__ A, const float* __restrict__ W,
               const float* __restrict__ bias, float* __restrict__ dst,
               int M, int headMode)
{
    extern __shared__ float smf[];
    uint32_t* As = (uint32_t*)smf;                 // [2][128*36]
    uint32_t* Bs = As + 2 * STAGE_W;               // [2][128*36]
    const uint32_t smb = smem_u32(smf);

    const int tid = threadIdx.x;
    const int lane = tid & 31;
    const int wid = tid >> 5;
    const int wm = wid >> 2;
    const int wn = wid & 3;
    const int rowBlk = blockIdx.y * 128;
    const int colBlk = blockIdx.x * 128;

    float acc[4][4][4];
    #pragma unroll
    for (int mi = 0; mi < 4; mi++)
        #pragma unroll
        for (int ni = 0; ni < 4; ni++)
            #pragma unroll
            for (int e = 0; e < 4; e++) acc[mi][ni][e] = 0.f;

    const int lrow = tid >> 1;
    const int lc0 = (tid & 1) * 16;
    const bool avalid = (rowBlk + lrow) < M;
    const float* aptr = A + (size_t)(rowBlk + lrow) * DIM + lc0;
    const float* wptr = W + (size_t)(colBlk + lrow) * DIM + lc0;
    const uint32_t thoff = ((uint32_t)lrow * LDT + (uint32_t)lc0) * 4u;   // bytes in stage

    const int NCH = DIM / KC;                      // 24

    // prologue: stage 0 fill
    {
        #pragma unroll
        for (int j = 0; j < 4; j++) {
            if (avalid) CP16(smb + thoff + j * 16, aptr + j * 4);
            CP16(smb + 2 * STAGE_W * 4 + thoff + j * 16, wptr + j * 4);
        }
        CP_COMMIT();
    }

    for (int ch = 0; ch < NCH; ch++) {
        if (ch + 1 < NCH) {
            const int k0 = (ch + 1) * KC;
            const uint32_t sb4 = ((ch + 1) & 1) * STAGE_W * 4;
            #pragma unroll
            for (int j = 0; j < 4; j++) {
                if (avalid) CP16(smb + sb4 + thoff + j * 16, aptr + k0 + j * 4);
                CP16(smb + 2 * STAGE_W * 4 + sb4 + thoff + j * 16, wptr + k0 + j * 4);
            }
            CP_COMMIT();
            CP_WAIT1();
        } else {
            CP_WAIT0();
        }
        __syncthreads();

        const uint32_t* A0 = As + (ch & 1) * STAGE_W;
        const uint32_t* B0 = Bs + (ch & 1) * STAGE_W;
        #pragma unroll
        for (int ks = 0; ks < 4; ks++) {
            const int c0 = ks * 8 + (lane & 3);
            uint32_t afr[4][4], bfr[4][2];
            #pragma unroll
            for (int mi = 0; mi < 4; mi++) {
                const int r = wm * 64 + mi * 16 + (lane >> 2);
                afr[mi][0] = A0[r * LDT + c0];
                afr[mi][1] = A0[(r + 8) * LDT + c0];
                afr[mi][2] = A0[r * LDT + c0 + 4];
                afr[mi][3] = A0[(r + 8) * LDT + c0 + 4];
            }
            #pragma unroll
            for (int ni = 0; ni < 4; ni++) {
                const int bn = wn * 32 + ni * 8 + (lane >> 2);
                bfr[ni][0] = B0[bn * LDT + c0];
                bfr[ni][1] = B0[bn * LDT + c0 + 4];
            }
            #pragma unroll
            for (int mi = 0; mi < 4; mi++)
                #pragma unroll
                for (int ni = 0; ni < 4; ni++)
                    mma_tf32(acc[mi][ni], afr[mi], bfr[ni]);
        }
        __syncthreads();   // compute(ch) done before fill(ch+2) overwrites this stage
    }

    float* epi = smf;
    #pragma unroll
    for (int mi = 0; mi < 4; mi++) {
        const int r = wm * 64 + mi * 16 + (lane >> 2);
        #pragma unroll
        for (int ni = 0; ni < 4; ni++) {
            const int c = wn * 32 + ni * 8 + 2 * (lane & 3);
            *(float2*)&epi[r * EPI_PITCH + c]       = make_float2(acc[mi][ni][0], acc[mi][ni][1]);
            *(float2*)&epi[(r + 8) * EPI_PITCH + c] = make_float2(acc[mi][ni][2], acc[mi][ni][3]);
        }
    }
    __syncthreads();

    for (int it = tid; it < 128 * 32; it += 256) {
        const int m2 = it >> 5;
        const int gm = rowBlk + m2;
        if (gm >= M) continue;
        const int c4 = (it & 31) * 4;
        const float4 bv = *(const float4*)(bias + colBlk + c4);
        float4 v;
        v.x = epi[m2 * EPI_PITCH + c4 + 0] + bv.x;
        v.y = epi[m2 * EPI_PITCH + c4 + 1] + bv.y;
        v.z = epi[m2 * EPI_PITCH + c4 + 2] + bv.z;
        v.w = epi[m2 * EPI_PITCH + c4 + 3] + bv.w;
        const int o = colBlk + c4;
        if (headMode == 1) {
            int b = gm / SEQ;
            int pos = gm - b * SEQ;
            int n = o >> 6, c = o & 63;
            *(float4*)(dst + (((size_t)(b * NH + n)) * KSEQ + pos) * HD + c) = v;
        } else if (headMode == 2) {
            int b = gm / SEQ;
            int pos = gm - b * SEQ;
            int n = o >> 6, c = o & 63;
            float* base = dst + ((size_t)(b * NH + n) * HD + c) * KSEQ + pos;
            base[0]        = v.x;
            base[KSEQ]     = v.y;
            base[2 * KSEQ] = v.z;
            base[3 * KSEQ] = v.w;
        } else {
            *(float4*)(dst + (size_t)gm * DIM + o) = v;
        }
    }
}

__global__ __launch_bounds__(256)
void gemm_qkv(const float* __restrict__ q, const float* __restrict__ k,
              const float* __restrict__ Wq, const float* __restrict__ bq,
              const float* __restrict__ Wk, const float* __restrict__ bk,
              const float* __restrict__ Wv, const float* __restrict__ bv,
              float* __restrict__ qh, float* __restrict__ kh, float* __restrict__ vt)
{
    const int z = blockIdx.z;
    const float* A    = (z == 0) ? q  : k;
    const float* W    = (z == 0) ? Wq : (z == 1) ? Wk : Wv;
    const float* bias = (z == 0) ? bq : (z == 1) ? bk : bv;
    float* dst        = (z == 0) ? qh : (z == 1) ? kh : vt;
    gemm_body(A, W, bias, dst, MROWS, (z == 2) ? 2 : 1);
}

__global__ __launch_bounds__(256)
void gemm_o(const float* __restrict__ A, const float* __restrict__ W,
            const float* __restrict__ bias, float* __restrict__ dst)
{
    gemm_body(A, W, bias, dst, MROWS, 0);
}

// ---------------- flash attention (R10 body; output pre-rounded) --------------
#define LDQ 68
#define TILE_WORDS (64 * 64)
#define NT (KSEQ / 64)
#define ATTN_SMEM ((4 * TILE_WORDS + 36 * 64) * 4 + 256)   // 75008 B

__global__ __launch_bounds__(128, 3)
void attn_mma(const float* __restrict__ qh, const float* __restrict__ kh,
              const float* __restrict__ vt,
              const float* __restrict__ rpt, const float* __restrict__ rph,
              const float* __restrict__ rpw,
              float* __restrict__ out)
{
    extern __shared__ float sm[];
    uint32_t* Kb = (uint32_t*)sm;
    uint32_t* Vb = Kb + 2 * TILE_WORDS;
    float* bias_sm = (float*)(Vb + 2 * TILE_WORDS);
    uint16_t* idx_sm = (uint16_t*)(bias_sm + 36 * 64);
    float* Qs = sm;

    const int tid = threadIdx.x;
    const int lane = tid & 31;
    const int wid = tid >> 5;
    const int q4 = lane & 3;
    const int r8 = lane >> 2;
    const int qblk = blockIdx.x;
    const int n = blockIdx.y;
    const int b = blockIdx.z;
    const int bn = b * NH + n;
    const int qbase = qblk * 64;
    const int r0 = wid * 16 + r8;

    const float* qbaseP = qh + (size_t)bn * KSEQ * HD;
    const float* kbaseP = kh + (size_t)bn * KSEQ * HD;
    const float* vtbase = vt + (size_t)bn * HD * KSEQ;

    const uint32_t smb = smem_u32(sm);
    const uint32_t kds = smb;
    const uint32_t vds = smb + 2 * TILE_WORDS * 4;

    {
        const int tx = tid & 15;
        const int ty = tid >> 4;
        const int c0 = tx * 4;
        #pragma unroll
        for (int it = 0; it < 8; it++) {
            int lq = ty + 8 * it;
            int gq = qbase + lq;
            float4 v = make_float4(0,0,0,0);
            if (gq < SEQ) v = *(const float4*)(qbaseP + (size_t)gq * HD + c0);
            Qs[(c0+0)*LDQ + lq] = v.x;
            Qs[(c0+1)*LDQ + lq] = v.y;
            Qs[(c0+2)*LDQ + lq] = v.z;
            Qs[(c0+3)*LDQ + lq] = v.w;
        }
    }
    __syncthreads();

    for (int idx = tid; idx < 64 * 36; idx += 128) {
        int lq = idx & 63;
        int j  = idx >> 6;
        int gq = qbase + lq;
        if (gq >= SEQ) gq = SEQ - 1;
        int t = gq / (QHH * QW);
        int rem = gq - t * (QHH * QW);
        int h = rem / QW;
        int w = rem - h * QW;
        const float* r;
        if (j < 8)       r = rpt + (size_t)(t - j + QT - 1) * HD;
        else if (j < 22) r = rph + (size_t)(h - (j - 8) + QHH - 1) * HD;
        else             r = rpw + (size_t)(w - (j - 22) + QW - 1) * HD;
        float acc = 0.f;
        #pragma unroll
        for (int c = 0; c < HD; c++) acc += Qs[c*LDQ + lq] * r[c];
        const int pos = (lq & 48) + ((lq & 7) << 1) + ((lq >> 3) & 1);
        bias_sm[j * 64 + pos] = acc * LOG2E;
    }
    if (tid < 64) idx_sm[tid] = pack_idx(tid);

    const float QSCALE = 0.125f * LOG2E;
    uint32_t qa[8][4];
    #pragma unroll
    for (int ks = 0; ks < 8; ks++) {
        const int pc = ks * 8 + 2 * q4;
        qa[ks][0] = f2tf32(QSCALE * Qs[pc*LDQ + r0]);
        qa[ks][1] = f2tf32(QSCALE * Qs[pc*LDQ + r0 + 8]);
        qa[ks][2] = f2tf32(QSCALE * Qs[(pc+1)*LDQ + r0]);
        qa[ks][3] = f2tf32(QSCALE * Qs[(pc+1)*LDQ + r0 + 8]);
    }
    __syncthreads();

    const int frow  = tid >> 1;
    const int cb16  = (tid & 1) * 8;
    const uint32_t xf = (uint32_t)((frow & 7) << 1);
    const float* krB = kbaseP + (size_t)frow * HD;
    const float* vrB = vtbase + (size_t)frow * KSEQ;

    {
        #pragma unroll
        for (int j = 0; j < 8; j++) {
            const int c16 = cb16 + j;
            const uint32_t pw = (uint32_t)frow * 64u + ((uint32_t)c16 ^ xf) * 4u;
            CP16(kds + pw * 4, krB + c16 * 4);
            CP16(vds + pw * 4, vrB + c16 * 4);
        }
        CP_COMMIT();
    }

    float accO[8][4];
    #pragma unroll
    for (int nb = 0; nb < 8; nb++)
        #pragma unroll
        for (int e = 0; e < 4; e++) accO[nb][e] = 0.f;
    float l0 = 0.f, l1 = 0.f;

    const int posr = (r0 & 48) + ((r0 & 7) << 1);
    const uint32_t xv = (uint32_t)(r8 << 3);

    for (int ti = 0; ti < NT; ti++) {
        CP_WAIT0();
        __syncthreads();

        if (ti + 1 < NT) {
            const int nb4 = ((ti + 1) & 1) * TILE_WORDS * 4;
            const float* kr = krB + (size_t)(ti + 1) * 64 * HD;
            const float* vr = vrB + (ti + 1) * 64;
            #pragma unroll
            for (int j = 0; j < 8; j++) {
                const int c16 = cb16 + j;
                const uint32_t pw = (uint32_t)frow * 64u + ((uint32_t)c16 ^ xf) * 4u;
                CP16(kds + nb4 + pw * 4, kr + c16 * 4);
                CP16(vds + nb4 + pw * 4, vr + c16 * 4);
            }
            CP_COMMIT();
            if (tid < 64) idx_sm[((ti + 1) & 1) * 64 + tid] = pack_idx((ti + 1) * 64 + tid);
        }

        const uint32_t* K0 = Kb + (ti & 1) * TILE_WORDS;
        const uint32_t* V0 = Vb + (ti & 1) * TILE_WORDS;
        const uint16_t* idxc = idx_sm + (ti & 1) * 64;
        const int kb = ti * 64;

        float sc[8][4];
        #pragma unroll
        for (int nb = 0; nb < 8; nb++)
            #pragma unroll
            for (int e = 0; e < 4; e++) sc[nb][e] = 0.f;
        #pragma unroll
        for (int ks = 0; ks < 8; ks++) {
            const uint32_t pcx = ((uint32_t)(ks * 8 + 2 * q4)) ^ xv;
            #pragma unroll
            for (int nb = 0; nb < 8; nb++) {
                uint2 bfr = *(const uint2*)&K0[(nb * 8 + r8) * 64 + pcx];
                mma_tf32(sc[nb], qa[ks], (const uint32_t*)&bfr);
            }
        }

        if (ti < NT - 1) {
            #pragma unroll
            for (int nb = 0; nb < 8; nb++) {
                const int col = nb * 8 + 2 * q4;
                #pragma unroll
                for (int j = 0; j < 2; j++) {
                    const uint32_t e = idxc[col + j];
                    float2 bt = *(const float2*)&bias_sm[(e & 7) * 64 + posr];
                    float2 bh = *(const float2*)&bias_sm[(8 + ((e >> 3) & 15)) * 64 + posr];
                    float2 bw = *(const float2*)&bias_sm[(22 + (e >> 7)) * 64 + posr];
                    sc[nb][j]     += bt.x + bh.x + bw.x;
                    sc[nb][j + 2] += bt.y + bh.y + bw.y;
                }
            }
        } else {
            #pragma unroll
            for (int nb = 0; nb < 8; nb++) {
                const int col = nb * 8 + 2 * q4;
                #pragma unroll
                for (int j = 0; j < 2; j++) {
                    if (kb + col + j < SEQ) {
                        const uint32_t e = idxc[col + j];
                        float2 bt = *(const float2*)&bias_sm[(e & 7) * 64 + posr];
                        float2 bh = *(const float2*)&bias_sm[(8 + ((e >> 3) & 15)) * 64 + posr];
                        float2 bw = *(const float2*)&bias_sm[(22 + (e >> 7)) * 64 + posr];
                        sc[nb][j]     += bt.x + bh.x + bw.x;
                        sc[nb][j + 2] += bt.y + bh.y + bw.y;
                    } else {
                        sc[nb][j] = -1e30f;
                        sc[nb][j + 2] = -1e30f;
                    }
                }
            }
        }

        #pragma unroll
        for (int nb = 0; nb < 8; nb++) {
            sc[nb][0] = ex2(sc[nb][0]);
            sc[nb][1] = ex2(sc[nb][1]);
            sc[nb][2] = ex2(sc[nb][2]);
            sc[nb][3] = ex2(sc[nb][3]);
            l0 += sc[nb][0] + sc[nb][1];
            l1 += sc[nb][2] + sc[nb][3];
        }

        #pragma unroll
        for (int kc = 0; kc < 8; kc++) {
            uint32_t pa[4];
            pa[0] = f2tf32(sc[kc][0]);
            pa[1] = f2tf32(sc[kc][2]);
            pa[2] = f2tf32(sc[kc][1]);
            pa[3] = f2tf32(sc[kc][3]);
            const uint32_t pkx = ((uint32_t)(kc * 8 + 2 * q4)) ^ xv;
            #pragma unroll
            for (int nb = 0; nb < 8; nb++) {
                uint2 bfr = *(const uint2*)&V0[(nb * 8 + r8) * 64 + pkx];
                mma_tf32(accO[nb], pa, (const uint32_t*)&bfr);
            }
        }
    }

    l0 += __shfl_xor_sync(0xffffffffu, l0, 1);
    l0 += __shfl_xor_sync(0xffffffffu, l0, 2);
    l1 += __shfl_xor_sync(0xffffffffu, l1, 1);
    l1 += __shfl_xor_sync(0xffffffffu, l1, 2);
    const float inv0 = 1.f / l0;
    const float inv1 = 1.f / l1;
    const int gq0 = qbase + r0;
    const int gq1 = gq0 + 8;
    #pragma unroll
    for (int nb = 0; nb < 8; nb++) {
        const int col0 = n * HD + nb * 8 + 2 * q4;
        if (gq0 < SEQ) {
            float2 o0 = make_float2(
                __uint_as_float(f2tf32(accO[nb][0] * inv0)),
                __uint_as_float(f2tf32(accO[nb][1] * inv0)));
            *(float2*)(out + ((size_t)b * SEQ + gq0) * DIM + col0) = o0;
        }
        if (gq1 < SEQ) {
            float2 o1 = make_float2(
                __uint_as_float(f2tf32(accO[nb][2] * inv1)),
                __uint_as_float(f2tf32(accO[nb][3] * inv1)));
            *(float2*)(out + ((size_t)b * SEQ + gq1) * DIM + col0) = o1;
        }
    }
}

// ---------------- launch ------------------------------------------------------
extern "C" void kernel_launch(void* const* d_in, const int* in_sizes, int n_in,
                              void* d_out, int out_size)
{
    (void)in_sizes; (void)n_in; (void)out_size;
    const float* q   = (const float*)d_in[0];
    const float* k   = (const float*)d_in[1];
    const float* Wq  = (const float*)d_in[2];
    const float* bq  = (const float*)d_in[3];
    const float* Wk  = (const float*)d_in[4];
    const float* bk  = (const float*)d_in[5];
    const float* Wv  = (const float*)d_in[6];
    const float* bv  = (const float*)d_in[7];
    const float* Wo  = (const float*)d_in[8];
    const float* bo  = (const float*)d_in[9];
    const float* rpt = (const float*)d_in[10];
    const float* rph = (const float*)d_in[11];
    const float* rpw = (const float*)d_in[12];
    float* out = (float*)d_out;

    float *p_qh, *p_kh, *p_vt, *p_attn;
    float *p_wq, *p_wk, *p_wv, *p_wo, *p_qr, *p_kr;
    cudaGetSymbolAddress((void**)&p_qh,   g_qh);
    cudaGetSymbolAddress((void**)&p_kh,   g_kh);
    cudaGetSymbolAddress((void**)&p_vt,   g_vt);
    cudaGetSymbolAddress((void**)&p_attn, g_attn);
    cudaGetSymbolAddress((void**)&p_wq,   g_wq);
    cudaGetSymbolAddress((void**)&p_wk,   g_wk);
    cudaGetSymbolAddress((void**)&p_wv,   g_wv);
    cudaGetSymbolAddress((void**)&p_wo,   g_wo);
    cudaGetSymbolAddress((void**)&p_qr,   g_qr);
    cudaGetSymbolAddress((void**)&p_kr,   g_kr);

    static int smem_set = 0;
    if (!smem_set) {
        cudaFuncSetAttribute(gemm_qkv,
                             cudaFuncAttributeMaxDynamicSharedMemorySize, GEMM_SMEM);
        cudaFuncSetAttribute(gemm_o,
                             cudaFuncAttributeMaxDynamicSharedMemorySize, GEMM_SMEM);
        cudaFuncSetAttribute(attn_mma,
                             cudaFuncAttributeMaxDynamicSharedMemorySize, ATTN_SMEM);
        smem_set = 1;
    }

    // prepass: tf32-RNA round weights + activations into scratch
    const int W4 = DIM * DIM / 4;          // 147456
    const int A4 = MROWS * DIM / 4;        // 602112
    round_pass<<<(W4 + 255) / 256, 256>>>(Wq, p_wq, W4);
    round_pass<<<(W4 + 255) / 256, 256>>>(Wk, p_wk, W4);
    round_pass<<<(W4 + 255) / 256, 256>>>(Wv, p_wv, W4);
    round_pass<<<(W4 + 255) / 256, 256>>>(Wo, p_wo, W4);
    round_pass<<<(A4 + 255) / 256, 256>>>(q, p_qr, A4);
    round_pass<<<(A4 + 255) / 256, 256>>>(k, p_kr, A4);

    dim3 qkvGrid(DIM / 128, (MROWS + 127) / 128, 3);   // 6 x 25 x 3
    gemm_qkv<<<qkvGrid, 256, GEMM_SMEM>>>(p_qr, p_kr, p_wq, bq, p_wk, bk, p_wv, bv,
                                          p_qh, p_kh, p_vt);

    dim3 attnGrid((SEQ + 63) / 64, NH, BATCH);         // 25 x 12 x 2
    attn_mma<<<attnGrid, 128, ATTN_SMEM>>>(p_qh, p_kh, p_vt, rpt, rph, rpw, p_attn);

    dim3 oGrid(DIM / 128, (MROWS + 127) / 128);        // 6 x 25
    gemm_o<<<oGrid, 256, GEMM_SMEM>>>(p_attn, p_wo, bo, out);
}

// round 12
// speedup vs baseline: 1.0248x; 1.0248x over previous
#include <cuda_runtime.h>
#include <cstdint>
#include <math.h>

#define BATCH 2
#define NH    12
#define HD    64
#define DIM   768
#define QT    8
#define QHH   14
#define QW    14
#define SEQ   1568
#define KSEQ  1600
#define MROWS 3136
#define LOG2E 1.44269504f

// ---------------- scratch ------------------------------------------------------
__device__ float g_qh[BATCH*NH*KSEQ*HD];    // [bn][k][c]
__device__ float g_kh[BATCH*NH*KSEQ*HD];    // [bn][k][c]  (pad rows stay 0)
__device__ float g_vt[BATCH*NH*HD*KSEQ];    // [bn][c][k]  (pad cols stay 0)
__device__ float g_attn[MROWS*DIM];
// pre-rounded (tf32-RNA) copies
__device__ float g_wq[DIM*DIM];
__device__ float g_wk[DIM*DIM];
__device__ float g_wv[DIM*DIM];
__device__ float g_wo[DIM*DIM];
__device__ float g_qr[MROWS*DIM];
__device__ float g_kr[MROWS*DIM];

// ---------------- helpers ------------------------------------------------------
__device__ __forceinline__ uint32_t f2tf32(float x) {
    uint32_t r;
    asm("cvt.rna.tf32.f32 %0, %1;" : "=r"(r) : "f"(x));
    return r;
}
__device__ __forceinline__ float ex2(float x) {
    float r;
    asm("ex2.approx.ftz.f32 %0, %1;" : "=f"(r) : "f"(x));
    return r;
}
__device__ __forceinline__ void mma_tf32(float* c, const uint32_t* a, const uint32_t* b) {
    asm volatile(
        "mma.sync.aligned.m16n8k8.row.col.f32.tf32.tf32.f32 "
        "{%0,%1,%2,%3}, {%4,%5,%6,%7}, {%8,%9}, {%0,%1,%2,%3};"
        : "+f"(c[0]), "+f"(c[1]), "+f"(c[2]), "+f"(c[3])
        : "r"(a[0]), "r"(a[1]), "r"(a[2]), "r"(a[3]), "r"(b[0]), "r"(b[1]));
}
__device__ __forceinline__ uint32_t smem_u32(const void* p) {
    uint32_t a;
    asm("{ .reg .u64 t; cvta.to.shared.u64 t, %1; cvt.u32.u64 %0, t; }" : "=r"(a) : "l"(p));
    return a;
}
#define CP16(dst, src) \
    asm volatile("cp.async.cg.shared.global [%0], [%1], 16;" :: "r"(dst), "l"(src))
#define CP_COMMIT() asm volatile("cp.async.commit_group;" ::: "memory")
#define CP_WAIT0()  asm volatile("cp.async.wait_group 0;" ::: "memory")
#define CP_WAIT1()  asm volatile("cp.async.wait_group 1;" ::: "memory")

__device__ __forceinline__ uint16_t pack_idx(int gk) {
    int gq = gk < SEQ ? gk : SEQ - 1;
    int kt = gq / (QHH * QW);
    int rem = gq - kt * (QHH * QW);
    int khh = rem / QW;
    int kww = rem - khh * QW;
    return (uint16_t)(kt | (khh << 3) | (kww << 7));
}

// ---------------- fused tf32-RNA rounding prepass (single launch) -------------
#define W4 (DIM * DIM / 4)          // 147456 float4, 576 blocks
#define A4 (MROWS * DIM / 4)        // 602112 float4, 2352 blocks
#define PRE_BLOCKS (4 * 576 + 2 * 2352)   // 7008

__global__ __launch_bounds__(256)
void round_all(const float* __restrict__ Wq, const float* __restrict__ Wk,
               const float* __restrict__ Wv, const float* __restrict__ Wo,
               const float* __restrict__ q,  const float* __restrict__ k,
               float* __restrict__ wq, float* __restrict__ wk,
               float* __restrict__ wv, float* __restrict__ wo,
               float* __restrict__ qr, float* __restrict__ kr)
{
    int blk = blockIdx.x;
    const float* src;
    float* dst;
    int base;
    if      (blk < 576)  { src = Wq; dst = wq; base = 0; }
    else if (blk < 1152) { src = Wk; dst = wk; base = 576; }
    else if (blk < 1728) { src = Wv; dst = wv; base = 1152; }
    else if (blk < 2304) { src = Wo; dst = wo; base = 1728; }
    else if (blk < 4656) { src = q;  dst = qr; base = 2304; }
    else                 { src = k;  dst = kr; base = 4656; }
    int i = (blk - base) * 256 + threadIdx.x;
    float4 v = ((const float4*)src)[i];
    uint4 u = make_uint4(f2tf32(v.x), f2tf32(v.y), f2tf32(v.z), f2tf32(v.w));
    ((uint4*)dst)[i] = u;
}

// ---------------- tf32 mma GEMM: cp.async staged + v2 relabeled fragments -----
#define KC 32
#define LDT 40                          // pitch: conflict-free v2 fragment loads
#define STAGE_W (128 * LDT)             // 5120 words per matrix per stage
#define EPI_PITCH 132
#define GEMM_SMEM (4 * STAGE_W * 4)     // 81920 B (>= epilogue 67584)

__device__ __forceinline__
void gemm_body(const float* __restrict__ A, const float* __restrict__ W,
               const float* __restrict__ bias, float* __restrict__ dst,
               int M, int headMode)
{
    extern __shared__ float smf[];
    uint32_t* As = (uint32_t*)smf;                 // [2][128*40]
    uint32_t* Bs = As + 2 * STAGE_W;               // [2][128*40]
    const uint32_t smb = smem_u32(smf);

    const int tid = threadIdx.x;
    const int lane = tid & 31;
    const int wid = tid >> 5;
    const int wm = wid >> 2;
    const int wn = wid & 3;
    const int rowBlk = blockIdx.y * 128;
    const int colBlk = blockIdx.x * 128;
    const int q4 = lane & 3;
    const int g4 = lane >> 2;

    float acc[4][4][4];
    #pragma unroll
    for (int mi = 0; mi < 4; mi++)
        #pragma unroll
        for (int ni = 0; ni < 4; ni++)
            #pragma unroll
            for (int e = 0; e < 4; e++) acc[mi][ni][e] = 0.f;

    const int lrow = tid >> 1;
    const int lc0 = (tid & 1) * 16;
    const bool avalid = (rowBlk + lrow) < M;
    const float* aptr = A + (size_t)(rowBlk + lrow) * DIM + lc0;
    const float* wptr = W + (size_t)(colBlk + lrow) * DIM + lc0;
    const uint32_t thoff = ((uint32_t)lrow * LDT + (uint32_t)lc0) * 4u;   // bytes

    const int NCH = DIM / KC;                      // 24

    {   // prologue: stage 0 fill
        #pragma unroll
        for (int j = 0; j < 4; j++) {
            if (avalid) CP16(smb + thoff + j * 16, aptr + j * 4);
            CP16(smb + 2 * STAGE_W * 4 + thoff + j * 16, wptr + j * 4);
        }
        CP_COMMIT();
    }

    for (int ch = 0; ch < NCH; ch++) {
        if (ch + 1 < NCH) {
            const int k0 = (ch + 1) * KC;
            const uint32_t sb4 = ((ch + 1) & 1) * STAGE_W * 4;
            #pragma unroll
            for (int j = 0; j < 4; j++) {
                if (avalid) CP16(smb + sb4 + thoff + j * 16, aptr + k0 + j * 4);
                CP16(smb + 2 * STAGE_W * 4 + sb4 + thoff + j * 16, wptr + k0 + j * 4);
            }
            CP_COMMIT();
            CP_WAIT1();
        } else {
            CP_WAIT0();
        }
        __syncthreads();

        const uint32_t* A0 = As + (ch & 1) * STAGE_W;
        const uint32_t* B0 = Bs + (ch & 1) * STAGE_W;
        #pragma unroll
        for (int ks = 0; ks < 4; ks++) {
            // relabeled contraction: thread q4 owns physical k-pair {2q4, 2q4+1}
            const int pc = ks * 8 + 2 * q4;
            uint32_t afr[4][4], bfr[4][2];
            #pragma unroll
            for (int mi = 0; mi < 4; mi++) {
                const int r = wm * 64 + mi * 16 + g4;
                uint2 u0 = *(const uint2*)&A0[r * LDT + pc];
                uint2 u1 = *(const uint2*)&A0[(r + 8) * LDT + pc];
                afr[mi][0] = u0.x; afr[mi][1] = u1.x;
                afr[mi][2] = u0.y; afr[mi][3] = u1.y;
            }
            #pragma unroll
            for (int ni = 0; ni < 4; ni++) {
                const int bn = wn * 32 + ni * 8 + g4;
                uint2 bf = *(const uint2*)&B0[bn * LDT + pc];
                bfr[ni][0] = bf.x; bfr[ni][1] = bf.y;
            }
            #pragma unroll
            for (int mi = 0; mi < 4; mi++)
                #pragma unroll
                for (int ni = 0; ni < 4; ni++)
                    mma_tf32(acc[mi][ni], afr[mi], bfr[ni]);
        }
        __syncthreads();
    }

    float* epi = smf;
    #pragma unroll
    for (int mi = 0; mi < 4; mi++) {
        const int r = wm * 64 + mi * 16 + g4;
        #pragma unroll
        for (int ni = 0; ni < 4; ni++) {
            const int c = wn * 32 + ni * 8 + 2 * q4;
            *(float2*)&epi[r * EPI_PITCH + c]       = make_float2(acc[mi][ni][0], acc[mi][ni][1]);
            *(float2*)&epi[(r + 8) * EPI_PITCH + c] = make_float2(acc[mi][ni][2], acc[mi][ni][3]);
        }
    }
    __syncthreads();

    for (int it = tid; it < 128 * 32; it += 256) {
        const int m2 = it >> 5;
        const int gm = rowBlk + m2;
        if (gm >= M) continue;
        const int c4 = (it & 31) * 4;
        const float4 bv = *(const float4*)(bias + colBlk + c4);
        float4 v;
        v.x = epi[m2 * EPI_PITCH + c4 + 0] + bv.x;
        v.y = epi[m2 * EPI_PITCH + c4 + 1] + bv.y;
        v.z = epi[m2 * EPI_PITCH + c4 + 2] + bv.z;
        v.w = epi[m2 * EPI_PITCH + c4 + 3] + bv.w;
        const int o = colBlk + c4;
        if (headMode == 1) {
            int b = gm / SEQ;
            int pos = gm - b * SEQ;
            int n = o >> 6, c = o & 63;
            *(float4*)(dst + (((size_t)(b * NH + n)) * KSEQ + pos) * HD + c) = v;
        } else if (headMode == 2) {
            int b = gm / SEQ;
            int pos = gm - b * SEQ;
            int n = o >> 6, c = o & 63;
            float* base = dst + ((size_t)(b * NH + n) * HD + c) * KSEQ + pos;
            base[0]        = v.x;
            base[KSEQ]     = v.y;
            base[2 * KSEQ] = v.z;
            base[3 * KSEQ] = v.w;
        } else {
            *(float4*)(dst + (size_t)gm * DIM + o) = v;
        }
    }
}

__global__ __launch_bounds__(256)
void gemm_qkv(const float* __restrict__ q, const float* __restrict__ k,
              const float* __restrict__ Wq, const float* __restrict__ bq,
              const float* __restrict__ Wk, const float* __restrict__ bk,
              const float* __restrict__ Wv, const float* __restrict__ bv,
              float* __restrict__ qh, float* __restrict__ kh, float* __restrict__ vt)
{
    const int z = blockIdx.z;
    const float* A    = (z == 0) ? q  : k;
    const float* W    = (z == 0) ? Wq : (z == 1) ? Wk : Wv;
    const float* bias = (z == 0) ? bq : (z == 1) ? bk : bv;
    float* dst        = (z == 0) ? qh : (z == 1) ? kh : vt;
    gemm_body(A, W, bias, dst, MROWS, (z == 2) ? 2 : 1);
}

__global__ __launch_bounds__(256)
void gemm_o(const float* __restrict__ A, const float* __restrict__ W,
            const float* __restrict__ bias, float* __restrict__ dst)
{
    gemm_body(A, W, bias, dst, MROWS, 0);
}

// ---------------- flash attention (R10 body; output pre-rounded) --------------
#define LDQ 68
#define TILE_WORDS (64 * 64)
#define NT (KSEQ / 64)
#define ATTN_SMEM ((4 * TILE_WORDS + 36 * 64) * 4 + 256)   // 75008 B

__global__ __launch_bounds__(128, 3)
void attn_mma(const float* __restrict__ qh, const float* __restrict__ kh,
              const float* __restrict__ vt,
              const float* __restrict__ rpt, const float* __restrict__ rph,
              const float* __restrict__ rpw,
              float* __restrict__ out)
{
    extern __shared__ float sm[];
    uint32_t* Kb = (uint32_t*)sm;
    uint32_t* Vb = Kb + 2 * TILE_WORDS;
    float* bias_sm = (float*)(Vb + 2 * TILE_WORDS);
    uint16_t* idx_sm = (uint16_t*)(bias_sm + 36 * 64);
    float* Qs = sm;

    const int tid = threadIdx.x;
    const int lane = tid & 31;
    const int wid = tid >> 5;
    const int q4 = lane & 3;
    const int r8 = lane >> 2;
    const int qblk = blockIdx.x;
    const int n = blockIdx.y;
    const int b = blockIdx.z;
    const int bn = b * NH + n;
    const int qbase = qblk * 64;
    const int r0 = wid * 16 + r8;

    const float* qbaseP = qh + (size_t)bn * KSEQ * HD;
    const float* kbaseP = kh + (size_t)bn * KSEQ * HD;
    const float* vtbase = vt + (size_t)bn * HD * KSEQ;

    const uint32_t smb = smem_u32(sm);
    const uint32_t kds = smb;
    const uint32_t vds = smb + 2 * TILE_WORDS * 4;

    {
        const int tx = tid & 15;
        const int ty = tid >> 4;
        const int c0 = tx * 4;
        #pragma unroll
        for (int it = 0; it < 8; it++) {
            int lq = ty + 8 * it;
            int gq = qbase + lq;
            float4 v = make_float4(0,0,0,0);
            if (gq < SEQ) v = *(const float4*)(qbaseP + (size_t)gq * HD + c0);
            Qs[(c0+0)*LDQ + lq] = v.x;
            Qs[(c0+1)*LDQ + lq] = v.y;
            Qs[(c0+2)*LDQ + lq] = v.z;
            Qs[(c0+3)*LDQ + lq] = v.w;
        }
    }
    __syncthreads();

    for (int idx = tid; idx < 64 * 36; idx += 128) {
        int lq = idx & 63;
        int j  = idx >> 6;
        int gq = qbase + lq;
        if (gq >= SEQ) gq = SEQ - 1;
        int t = gq / (QHH * QW);
        int rem = gq - t * (QHH * QW);
        int h = rem / QW;
        int w = rem - h * QW;
        const float* r;
        if (j < 8)       r = rpt + (size_t)(t - j + QT - 1) * HD;
        else if (j < 22) r = rph + (size_t)(h - (j - 8) + QHH - 1) * HD;
        else             r = rpw + (size_t)(w - (j - 22) + QW - 1) * HD;
        float acc = 0.f;
        #pragma unroll
        for (int c = 0; c < HD; c++) acc += Qs[c*LDQ + lq] * r[c];
        const int pos = (lq & 48) + ((lq & 7) << 1) + ((lq >> 3) & 1);
        bias_sm[j * 64 + pos] = acc * LOG2E;
    }
    if (tid < 64) idx_sm[tid] = pack_idx(tid);

    const float QSCALE = 0.125f * LOG2E;
    uint32_t qa[8][4];
    #pragma unroll
    for (int ks = 0; ks < 8; ks++) {
        const int pc = ks * 8 + 2 * q4;
        qa[ks][0] = f2tf32(QSCALE * Qs[pc*LDQ + r0]);
        qa[ks][1] = f2tf32(QSCALE * Qs[pc*LDQ + r0 + 8]);
        qa[ks][2] = f2tf32(QSCALE * Qs[(pc+1)*LDQ + r0]);
        qa[ks][3] = f2tf32(QSCALE * Qs[(pc+1)*LDQ + r0 + 8]);
    }
    __syncthreads();

    const int frow  = tid >> 1;
    const int cb16  = (tid & 1) * 8;
    const uint32_t xf = (uint32_t)((frow & 7) << 1);
    const float* krB = kbaseP + (size_t)frow * HD;
    const float* vrB = vtbase + (size_t)frow * KSEQ;

    {
        #pragma unroll
        for (int j = 0; j < 8; j++) {
            const int c16 = cb16 + j;
            const uint32_t pw = (uint32_t)frow * 64u + ((uint32_t)c16 ^ xf) * 4u;
            CP16(kds + pw * 4, krB + c16 * 4);
            CP16(vds + pw * 4, vrB + c16 * 4);
        }
        CP_COMMIT();
    }

    float accO[8][4];
    #pragma unroll
    for (int nb = 0; nb < 8; nb++)
        #pragma unroll
        for (int e = 0; e < 4; e++) accO[nb][e] = 0.f;
    float l0 = 0.f, l1 = 0.f;

    const int posr = (r0 & 48) + ((r0 & 7) << 1);
    const uint32_t xv = (uint32_t)(r8 << 3);

    for (int ti = 0; ti < NT; ti++) {
        CP_WAIT0();
        __syncthreads();

        if (ti + 1 < NT) {
            const int nb4 = ((ti + 1) & 1) * TILE_WORDS * 4;
            const float* kr = krB + (size_t)(ti + 1) * 64 * HD;
            const float* vr = vrB + (ti + 1) * 64;
            #pragma unroll
            for (int j = 0; j < 8; j++) {
                const int c16 = cb16 + j;
                const uint32_t pw = (uint32_t)frow * 64u + ((uint32_t)c16 ^ xf) * 4u;
                CP16(kds + nb4 + pw * 4, kr + c16 * 4);
                CP16(vds + nb4 + pw * 4, vr + c16 * 4);
            }
            CP_COMMIT();
            if (tid < 64) idx_sm[((ti + 1) & 1) * 64 + tid] = pack_idx((ti + 1) * 64 + tid);
        }

        const uint32_t* K0 = Kb + (ti & 1) * TILE_WORDS;
        const uint32_t* V0 = Vb + (ti & 1) * TILE_WORDS;
        const uint16_t* idxc = idx_sm + (ti & 1) * 64;
        const int kb = ti * 64;

        float sc[8][4];
        #pragma unroll
        for (int nb = 0; nb < 8; nb++)
            #pragma unroll
            for (int e = 0; e < 4; e++) sc[nb][e] = 0.f;
        #pragma unroll
        for (int ks = 0; ks < 8; ks++) {
            const uint32_t pcx = ((uint32_t)(ks * 8 + 2 * q4)) ^ xv;
            #pragma unroll
            for (int nb = 0; nb < 8; nb++) {
                uint2 bfr = *(const uint2*)&K0[(nb * 8 + r8) * 64 + pcx];
                mma_tf32(sc[nb], qa[ks], (const uint32_t*)&bfr);
            }
        }

        if (ti < NT - 1) {
            #pragma unroll
            for (int nb = 0; nb < 8; nb++) {
                const int col = nb * 8 + 2 * q4;
                #pragma unroll
                for (int j = 0; j < 2; j++) {
                    const uint32_t e = idxc[col + j];
                    float2 bt = *(const float2*)&bias_sm[(e & 7) * 64 + posr];
                    float2 bh = *(const float2*)&bias_sm[(8 + ((e >> 3) & 15)) * 64 + posr];
                    float2 bw = *(const float2*)&bias_sm[(22 + (e >> 7)) * 64 + posr];
                    sc[nb][j]     += bt.x + bh.x + bw.x;
                    sc[nb][j + 2] += bt.y + bh.y + bw.y;
                }
            }
        } else {
            #pragma unroll
            for (int nb = 0; nb < 8; nb++) {
                const int col = nb * 8 + 2 * q4;
                #pragma unroll
                for (int j = 0; j < 2; j++) {
                    if (kb + col + j < SEQ) {
                        const uint32_t e = idxc[col + j];
                        float2 bt = *(const float2*)&bias_sm[(e & 7) * 64 + posr];
                        float2 bh = *(const float2*)&bias_sm[(8 + ((e >> 3) & 15)) * 64 + posr];
                        float2 bw = *(const float2*)&bias_sm[(22 + (e >> 7)) * 64 + posr];
                        sc[nb][j]     += bt.x + bh.x + bw.x;
                        sc[nb][j + 2] += bt.y + bh.y + bw.y;
                    } else {
                        sc[nb][j] = -1e30f;
                        sc[nb][j + 2] = -1e30f;
                    }
                }
            }
        }

        #pragma unroll
        for (int nb = 0; nb < 8; nb++) {
            sc[nb][0] = ex2(sc[nb][0]);
            sc[nb][1] = ex2(sc[nb][1]);
            sc[nb][2] = ex2(sc[nb][2]);
            sc[nb][3] = ex2(sc[nb][3]);
            l0 += sc[nb][0] + sc[nb][1];
            l1 += sc[nb][2] + sc[nb][3];
        }

        #pragma unroll
        for (int kc = 0; kc < 8; kc++) {
            uint32_t pa[4];
            pa[0] = f2tf32(sc[kc][0]);
            pa[1] = f2tf32(sc[kc][2]);
            pa[2] = f2tf32(sc[kc][1]);
            pa[3] = f2tf32(sc[kc][3]);
            const uint32_t pkx = ((uint32_t)(kc * 8 + 2 * q4)) ^ xv;
            #pragma unroll
            for (int nb = 0; nb < 8; nb++) {
                uint2 bfr = *(const uint2*)&V0[(nb * 8 + r8) * 64 + pkx];
                mma_tf32(accO[nb], pa, (const uint32_t*)&bfr);
            }
        }
    }

    l0 += __shfl_xor_sync(0xffffffffu, l0, 1);
    l0 += __shfl_xor_sync(0xffffffffu, l0, 2);
    l1 += __shfl_xor_sync(0xffffffffu, l1, 1);
    l1 += __shfl_xor_sync(0xffffffffu, l1, 2);
    const float inv0 = 1.f / l0;
    const float inv1 = 1.f / l1;
    const int gq0 = qbase + r0;
    const int gq1 = gq0 + 8;
    #pragma unroll
    for (int nb = 0; nb < 8; nb++) {
        const int col0 = n * HD + nb * 8 + 2 * q4;
        if (gq0 < SEQ) {
            float2 o0 = make_float2(
                __uint_as_float(f2tf32(accO[nb][0] * inv0)),
                __uint_as_float(f2tf32(accO[nb][1] * inv0)));
            *(float2*)(out + ((size_t)b * SEQ + gq0) * DIM + col0) = o0;
        }
        if (gq1 < SEQ) {
            float2 o1 = make_float2(
                __uint_as_float(f2tf32(accO[nb][2] * inv1)),
                __uint_as_float(f2tf32(accO[nb][3] * inv1)));
            *(float2*)(out + ((size_t)b * SEQ + gq1) * DIM + col0) = o1;
        }
    }
}

// ---------------- launch ------------------------------------------------------
extern "C" void kernel_launch(void* const* d_in, const int* in_sizes, int n_in,
                              void* d_out, int out_size)
{
    (void)in_sizes; (void)n_in; (void)out_size;
    const float* q   = (const float*)d_in[0];
    const float* k   = (const float*)d_in[1];
    const float* Wq  = (const float*)d_in[2];
    const float* bq  = (const float*)d_in[3];
    const float* Wk  = (const float*)d_in[4];
    const float* bk  = (const float*)d_in[5];
    const float* Wv  = (const float*)d_in[6];
    const float* bv  = (const float*)d_in[7];
    const float* Wo  = (const float*)d_in[8];
    const float* bo  = (const float*)d_in[9];
    const float* rpt = (const float*)d_in[10];
    const float* rph = (const float*)d_in[11];
    const float* rpw = (const float*)d_in[12];
    float* out = (float*)d_out;

    float *p_qh, *p_kh, *p_vt, *p_attn;
    float *p_wq, *p_wk, *p_wv, *p_wo, *p_qr, *p_kr;
    cudaGetSymbolAddress((void**)&p_qh,   g_qh);
    cudaGetSymbolAddress((void**)&p_kh,   g_kh);
    cudaGetSymbolAddress((void**)&p_vt,   g_vt);
    cudaGetSymbolAddress((void**)&p_attn, g_attn);
    cudaGetSymbolAddress((void**)&p_wq,   g_wq);
    cudaGetSymbolAddress((void**)&p_wk,   g_wk);
    cudaGetSymbolAddress((void**)&p_wv,   g_wv);
    cudaGetSymbolAddress((void**)&p_wo,   g_wo);
    cudaGetSymbolAddress((void**)&p_qr,   g_qr);
    cudaGetSymbolAddress((void**)&p_kr,   g_kr);

    static int smem_set = 0;
    if (!smem_set) {
        cudaFuncSetAttribute(gemm_qkv,
                             cudaFuncAttributeMaxDynamicSharedMemorySize, GEMM_SMEM);
        cudaFuncSetAttribute(gemm_o,
                             cudaFuncAttributeMaxDynamicSharedMemorySize, GEMM_SMEM);
        cudaFuncSetAttribute(attn_mma,
                             cudaFuncAttributeMaxDynamicSharedMemorySize, ATTN_SMEM);
        smem_set = 1;
    }

    round_all<<<PRE_BLOCKS, 256>>>(Wq, Wk, Wv, Wo, q, k,
                                   p_wq, p_wk, p_wv, p_wo, p_qr, p_kr);

    dim3 qkvGrid(DIM / 128, (MROWS + 127) / 128, 3);   // 6 x 25 x 3
    gemm_qkv<<<qkvGrid, 256, GEMM_SMEM>>>(p_qr, p_kr, p_wq, bq, p_wk, bk, p_wv, bv,
                                          p_qh, p_kh, p_vt);

    dim3 attnGrid((SEQ + 63) / 64, NH, BATCH);         // 25 x 12 x 2
    attn_mma<<<attnGrid, 128, ATTN_SMEM>>>(p_qh, p_kh, p_vt, rpt, rph, rpw, p_attn);

    dim3 oGrid(DIM / 128, (MROWS + 127) / 128);        // 6 x 25
    gemm_o<<<oGrid, 256, GEMM_SMEM>>>(p_attn, p_wo, bo, out);
}

// round 13
// speedup vs baseline: 1.1466x; 1.1189x over previous
#include <cuda_runtime.h>
#include <cstdint>
#include <math.h>

#define BATCH 2
#define NH    12
#define HD    64
#define DIM   768
#define QT    8
#define QHH   14
#define QW    14
#define SEQ   1568
#define KSEQ  1600
#define MROWS 3136
#define LOG2E 1.44269504f

// ---------------- scratch ------------------------------------------------------
__device__ float g_qh[BATCH*NH*KSEQ*HD];
__device__ float g_kh[BATCH*NH*KSEQ*HD];
__device__ float g_vt[BATCH*NH*HD*KSEQ];
__device__ float g_attn[MROWS*DIM];
__device__ float g_wq[DIM*DIM];
__device__ float g_wk[DIM*DIM];
__device__ float g_wv[DIM*DIM];
__device__ float g_wo[DIM*DIM];
__device__ float g_qr[MROWS*DIM];
__device__ float g_kr[MROWS*DIM];

// ---------------- helpers ------------------------------------------------------
__device__ __forceinline__ uint32_t f2tf32(float x) {
    uint32_t r;
    asm("cvt.rna.tf32.f32 %0, %1;" : "=r"(r) : "f"(x));
    return r;
}
__device__ __forceinline__ float ex2(float x) {
    float r;
    asm("ex2.approx.ftz.f32 %0, %1;" : "=f"(r) : "f"(x));
    return r;
}
__device__ __forceinline__ void mma_tf32(float* c, const uint32_t* a, const uint32_t* b) {
    asm volatile(
        "mma.sync.aligned.m16n8k8.row.col.f32.tf32.tf32.f32 "
        "{%0,%1,%2,%3}, {%4,%5,%6,%7}, {%8,%9}, {%0,%1,%2,%3};"
        : "+f"(c[0]), "+f"(c[1]), "+f"(c[2]), "+f"(c[3])
        : "r"(a[0]), "r"(a[1]), "r"(a[2]), "r"(a[3]), "r"(b[0]), "r"(b[1]));
}
__device__ __forceinline__ uint32_t smem_u32(const void* p) {
    uint32_t a;
    asm("{ .reg .u64 t; cvta.to.shared.u64 t, %1; cvt.u32.u64 %0, t; }" : "=r"(a) : "l"(p));
    return a;
}
#define CP16(dst, src) \
    asm volatile("cp.async.cg.shared.global [%0], [%1], 16;" :: "r"(dst), "l"(src))
#define CP_COMMIT() asm volatile("cp.async.commit_group;" ::: "memory")
#define CP_WAIT0()  asm volatile("cp.async.wait_group 0;" ::: "memory")
#define CP_WAIT1()  asm volatile("cp.async.wait_group 1;" ::: "memory")

__device__ __forceinline__ uint16_t pack_idx(int gk) {
    int gq = gk < SEQ ? gk : SEQ - 1;
    int kt = gq / (QHH * QW);
    int rem = gq - kt * (QHH * QW);
    int khh = rem / QW;
    int kww = rem - khh * QW;
    return (uint16_t)(kt | (khh << 3) | (kww << 7));
}

// ---------------- fused tf32-RNA rounding prepass -----------------------------
#define PRE_BLOCKS (4 * 576 + 2 * 2352)

__global__ __launch_bounds__(256)
void round_all(const float* __restrict__ Wq, const float* __restrict__ Wk,
               const float* __restrict__ Wv, const float* __restrict__ Wo,
               const float* __restrict__ q,  const float* __restrict__ k,
               float* __restrict__ wq, float* __restrict__ wk,
               float* __restrict__ wv, float* __restrict__ wo,
               float* __restrict__ qr, float* __restrict__ kr)
{
    int blk = blockIdx.x;
    const float* src;
    float* dst;
    int base;
    if      (blk < 576)  { src = Wq; dst = wq; base = 0; }
    else if (blk < 1152) { src = Wk; dst = wk; base = 576; }
    else if (blk < 1728) { src = Wv; dst = wv; base = 1152; }
    else if (blk < 2304) { src = Wo; dst = wo; base = 1728; }
    else if (blk < 4656) { src = q;  dst = qr; base = 2304; }
    else                 { src = k;  dst = kr; base = 4656; }
    int i = (blk - base) * 256 + threadIdx.x;
    float4 v = ((const float4*)src)[i];
    uint4 u = make_uint4(f2tf32(v.x), f2tf32(v.y), f2tf32(v.z), f2tf32(v.w));
    ((uint4*)dst)[i] = u;
}

// ---------------- tf32 mma GEMM (R12 body, unchanged) -------------------------
#define KC 32
#define LDT 40
#define STAGE_W (128 * LDT)
#define EPI_PITCH 132
#define GEMM_SMEM (4 * STAGE_W * 4)

__device__ __forceinline__
void gemm_body(const float* __restrict__ A, const float* __restrict__ W,
               const float* __restrict__ bias, float* __restrict__ dst,
               int M, int headMode)
{
    extern __shared__ float smf[];
    uint32_t* As = (uint32_t*)smf;
    uint32_t* Bs = As + 2 * STAGE_W;
    const uint32_t smb = smem_u32(smf);

    const int tid = threadIdx.x;
    const int lane = tid & 31;
    const int wid = tid >> 5;
    const int wm = wid >> 2;
    const int wn = wid & 3;
    const int rowBlk = blockIdx.y * 128;
    const int colBlk = blockIdx.x * 128;
    const int q4 = lane & 3;
    const int g4 = lane >> 2;

    float acc[4][4][4];
    #pragma unroll
    for (int mi = 0; mi < 4; mi++)
        #pragma unroll
        for (int ni = 0; ni < 4; ni++)
            #pragma unroll
            for (int e = 0; e < 4; e++) acc[mi][ni][e] = 0.f;

    const int lrow = tid >> 1;
    const int lc0 = (tid & 1) * 16;
    const bool avalid = (rowBlk + lrow) < M;
    const float* aptr = A + (size_t)(rowBlk + lrow) * DIM + lc0;
    const float* wptr = W + (size_t)(colBlk + lrow) * DIM + lc0;
    const uint32_t thoff = ((uint32_t)lrow * LDT + (uint32_t)lc0) * 4u;

    const int NCH = DIM / KC;

    {
        #pragma unroll
        for (int j = 0; j < 4; j++) {
            if (avalid) CP16(smb + thoff + j * 16, aptr + j * 4);
            CP16(smb + 2 * STAGE_W * 4 + thoff + j * 16, wptr + j * 4);
        }
        CP_COMMIT();
    }

    for (int ch = 0; ch < NCH; ch++) {
        if (ch + 1 < NCH) {
            const int k0 = (ch + 1) * KC;
            const uint32_t sb4 = ((ch + 1) & 1) * STAGE_W * 4;
            #pragma unroll
            for (int j = 0; j < 4; j++) {
                if (avalid) CP16(smb + sb4 + thoff + j * 16, aptr + k0 + j * 4);
                CP16(smb + 2 * STAGE_W * 4 + sb4 + thoff + j * 16, wptr + k0 + j * 4);
            }
            CP_COMMIT();
            CP_WAIT1();
        } else {
            CP_WAIT0();
        }
        __syncthreads();

        const uint32_t* A0 = As + (ch & 1) * STAGE_W;
        const uint32_t* B0 = Bs + (ch & 1) * STAGE_W;
        #pragma unroll
        for (int ks = 0; ks < 4; ks++) {
            const int pc = ks * 8 + 2 * q4;
            uint32_t afr[4][4], bfr[4][2];
            #pragma unroll
            for (int mi = 0; mi < 4; mi++) {
                const int r = wm * 64 + mi * 16 + g4;
                uint2 u0 = *(const uint2*)&A0[r * LDT + pc];
                uint2 u1 = *(const uint2*)&A0[(r + 8) * LDT + pc];
                afr[mi][0] = u0.x; afr[mi][1] = u1.x;
                afr[mi][2] = u0.y; afr[mi][3] = u1.y;
            }
            #pragma unroll
            for (int ni = 0; ni < 4; ni++) {
                const int bn = wn * 32 + ni * 8 + g4;
                uint2 bf = *(const uint2*)&B0[bn * LDT + pc];
                bfr[ni][0] = bf.x; bfr[ni][1] = bf.y;
            }
            #pragma unroll
            for (int mi = 0; mi < 4; mi++)
                #pragma unroll
                for (int ni = 0; ni < 4; ni++)
                    mma_tf32(acc[mi][ni], afr[mi], bfr[ni]);
        }
        __syncthreads();
    }

    float* epi = smf;
    #pragma unroll
    for (int mi = 0; mi < 4; mi++) {
        const int r = wm * 64 + mi * 16 + g4;
        #pragma unroll
        for (int ni = 0; ni < 4; ni++) {
            const int c = wn * 32 + ni * 8 + 2 * q4;
            *(float2*)&epi[r * EPI_PITCH + c]       = make_float2(acc[mi][ni][0], acc[mi][ni][1]);
            *(float2*)&epi[(r + 8) * EPI_PITCH + c] = make_float2(acc[mi][ni][2], acc[mi][ni][3]);
        }
    }
    __syncthreads();

    for (int it = tid; it < 128 * 32; it += 256) {
        const int m2 = it >> 5;
        const int gm = rowBlk + m2;
        if (gm >= M) continue;
        const int c4 = (it & 31) * 4;
        const float4 bv = *(const float4*)(bias + colBlk + c4);
        float4 v;
        v.x = epi[m2 * EPI_PITCH + c4 + 0] + bv.x;
        v.y = epi[m2 * EPI_PITCH + c4 + 1] + bv.y;
        v.z = epi[m2 * EPI_PITCH + c4 + 2] + bv.z;
        v.w = epi[m2 * EPI_PITCH + c4 + 3] + bv.w;
        const int o = colBlk + c4;
        if (headMode == 1) {
            int b = gm / SEQ;
            int pos = gm - b * SEQ;
            int n = o >> 6, c = o & 63;
            *(float4*)(dst + (((size_t)(b * NH + n)) * KSEQ + pos) * HD + c) = v;
        } else if (headMode == 2) {
            int b = gm / SEQ;
            int pos = gm - b * SEQ;
            int n = o >> 6, c = o & 63;
            float* base = dst + ((size_t)(b * NH + n) * HD + c) * KSEQ + pos;
            base[0]        = v.x;
            base[KSEQ]     = v.y;
            base[2 * KSEQ] = v.z;
            base[3 * KSEQ] = v.w;
        } else {
            *(float4*)(dst + (size_t)gm * DIM + o) = v;
        }
    }
}

__global__ __launch_bounds__(256)
void gemm_qkv(const float* __restrict__ q, const float* __restrict__ k,
              const float* __restrict__ Wq, const float* __restrict__ bq,
              const float* __restrict__ Wk, const float* __restrict__ bk,
              const float* __restrict__ Wv, const float* __restrict__ bv,
              float* __restrict__ qh, float* __restrict__ kh, float* __restrict__ vt)
{
    const int z = blockIdx.z;
    const float* A    = (z == 0) ? q  : k;
    const float* W    = (z == 0) ? Wq : (z == 1) ? Wk : Wv;
    const float* bias = (z == 0) ? bq : (z == 1) ? bk : bv;
    float* dst        = (z == 0) ? qh : (z == 1) ? kh : vt;
    gemm_body(A, W, bias, dst, MROWS, (z == 2) ? 2 : 1);
}

__global__ __launch_bounds__(256)
void gemm_o(const float* __restrict__ A, const float* __restrict__ W,
            const float* __restrict__ bias, float* __restrict__ dst)
{
    gemm_body(A, W, bias, dst, MROWS, 0);
}

// ---------------- split-K flash attention: 256 thr, 8 warps, 2 K-groups -------
#define LDQ 68
#define TILE_WORDS (64 * 64)
#define NT (KSEQ / 64)
#define RED_PITCH 68
#define ATTN_SMEM ((4 * TILE_WORDS + 36 * 64) * 4 + 256)   // 75008 B

__global__ __launch_bounds__(256, 2)
void attn_mma(const float* __restrict__ qh, const float* __restrict__ kh,
              const float* __restrict__ vt,
              const float* __restrict__ rpt, const float* __restrict__ rph,
              const float* __restrict__ rpw,
              float* __restrict__ out)
{
    extern __shared__ float sm[];
    uint32_t* Kb = (uint32_t*)sm;
    uint32_t* Vb = Kb + 2 * TILE_WORDS;
    float* bias_sm = (float*)(Vb + 2 * TILE_WORDS);
    uint16_t* idx_sm = (uint16_t*)(bias_sm + 36 * 64);
    float* Qs = sm;
    float* red  = (float*)Kb;              // post-loop reduction [64][RED_PITCH]
    float* lred = (float*)Vb;              // post-loop row-sum partials [128]

    const int tid = threadIdx.x;
    const int lane = tid & 31;
    const int wid = tid >> 5;              // 0..7
    const int grp = wid >> 2;              // K-group 0/1
    const int lw  = wid & 3;
    const int nbo = grp * 4;               // this group's nb offset
    const int q4 = lane & 3;
    const int r8 = lane >> 2;
    const int qblk = blockIdx.x;
    const int n = blockIdx.y;
    const int b = blockIdx.z;
    const int bn = b * NH + n;
    const int qbase = qblk * 64;
    const int r0 = lw * 16 + r8;

    const float* qbaseP = qh + (size_t)bn * KSEQ * HD;
    const float* kbaseP = kh + (size_t)bn * KSEQ * HD;
    const float* vtbase = vt + (size_t)bn * HD * KSEQ;

    const uint32_t smb = smem_u32(sm);
    const uint32_t kds = smb;
    const uint32_t vds = smb + 2 * TILE_WORDS * 4;

    // ---- prologue: Q transposed [c][q] ----
    {
        const int tx = tid & 15;
        const int ty = tid >> 4;           // 0..15
        const int c0 = tx * 4;
        #pragma unroll
        for (int it = 0; it < 4; it++) {
            int lq = ty + 16 * it;
            int gq = qbase + lq;
            float4 v = make_float4(0,0,0,0);
            if (gq < SEQ) v = *(const float4*)(qbaseP + (size_t)gq * HD + c0);
            Qs[(c0+0)*LDQ + lq] = v.x;
            Qs[(c0+1)*LDQ + lq] = v.y;
            Qs[(c0+2)*LDQ + lq] = v.z;
            Qs[(c0+3)*LDQ + lq] = v.w;
        }
    }
    __syncthreads();

    // ---- bias tables (log2e-scaled) + idx table tile 0 ----
    for (int idx = tid; idx < 64 * 36; idx += 256) {
        int lq = idx & 63;
        int j  = idx >> 6;
        int gq = qbase + lq;
        if (gq >= SEQ) gq = SEQ - 1;
        int t = gq / (QHH * QW);
        int rem = gq - t * (QHH * QW);
        int h = rem / QW;
        int w = rem - h * QW;
        const float* r;
        if (j < 8)       r = rpt + (size_t)(t - j + QT - 1) * HD;
        else if (j < 22) r = rph + (size_t)(h - (j - 8) + QHH - 1) * HD;
        else             r = rpw + (size_t)(w - (j - 22) + QW - 1) * HD;
        float acc = 0.f;
        #pragma unroll
        for (int c = 0; c < HD; c++) acc += Qs[c*LDQ + lq] * r[c];
        const int pos = (lq & 48) + ((lq & 7) << 1) + ((lq >> 3) & 1);
        bias_sm[j * 64 + pos] = acc * LOG2E;
    }
    if (tid < 64) idx_sm[tid] = pack_idx(tid);

    // ---- Q fragments ----
    const float QSCALE = 0.125f * LOG2E;
    uint32_t qa[8][4];
    #pragma unroll
    for (int ks = 0; ks < 8; ks++) {
        const int pc = ks * 8 + 2 * q4;
        qa[ks][0] = f2tf32(QSCALE * Qs[pc*LDQ + r0]);
        qa[ks][1] = f2tf32(QSCALE * Qs[pc*LDQ + r0 + 8]);
        qa[ks][2] = f2tf32(QSCALE * Qs[(pc+1)*LDQ + r0]);
        qa[ks][3] = f2tf32(QSCALE * Qs[(pc+1)*LDQ + r0 + 8]);
    }
    __syncthreads();

    // ---- fill machinery: 256 threads, 8 CP16 each ----
    const int frow  = tid >> 2;            // 0..63
    const int cb16  = (tid & 3) * 4;       // chunk base
    const uint32_t xf = (uint32_t)((frow & 7) << 1);
    const float* krB = kbaseP + (size_t)frow * HD;
    const float* vrB = vtbase + (size_t)frow * KSEQ;

    {
        #pragma unroll
        for (int j = 0; j < 4; j++) {
            const int c16 = cb16 + j;
            const uint32_t pw = (uint32_t)frow * 64u + ((uint32_t)c16 ^ xf) * 4u;
            CP16(kds + pw * 4, krB + c16 * 4);
            CP16(vds + pw * 4, vrB + c16 * 4);
        }
        CP_COMMIT();
    }

    float accO[8][4];
    #pragma unroll
    for (int nb = 0; nb < 8; nb++)
        #pragma unroll
        for (int e = 0; e < 4; e++) accO[nb][e] = 0.f;
    float l0 = 0.f, l1 = 0.f;

    const int posr = (r0 & 48) + ((r0 & 7) << 1);
    const uint32_t xv = (uint32_t)(r8 << 3);

    for (int ti = 0; ti < NT; ti++) {
        CP_WAIT0();
        __syncthreads();

        if (ti + 1 < NT) {
            const int nb4 = ((ti + 1) & 1) * TILE_WORDS * 4;
            const float* kr = krB + (size_t)(ti + 1) * 64 * HD;
            const float* vr = vrB + (ti + 1) * 64;
            #pragma unroll
            for (int j = 0; j < 4; j++) {
                const int c16 = cb16 + j;
                const uint32_t pw = (uint32_t)frow * 64u + ((uint32_t)c16 ^ xf) * 4u;
                CP16(kds + nb4 + pw * 4, kr + c16 * 4);
                CP16(vds + nb4 + pw * 4, vr + c16 * 4);
            }
            CP_COMMIT();
            if (tid < 64) idx_sm[((ti + 1) & 1) * 64 + tid] = pack_idx((ti + 1) * 64 + tid);
        }

        const uint32_t* K0 = Kb + (ti & 1) * TILE_WORDS;
        const uint32_t* V0 = Vb + (ti & 1) * TILE_WORDS;
        const uint16_t* idxc = idx_sm + (ti & 1) * 64;
        const int kb = ti * 64;

        // ---- S over this group's 32 K-cols ----
        float sc[4][4];
        #pragma unroll
        for (int j = 0; j < 4; j++)
            #pragma unroll
            for (int e = 0; e < 4; e++) sc[j][e] = 0.f;
        #pragma unroll
        for (int ks = 0; ks < 8; ks++) {
            const uint32_t pcx = ((uint32_t)(ks * 8 + 2 * q4)) ^ xv;
            #pragma unroll
            for (int j = 0; j < 4; j++) {
                uint2 bfr = *(const uint2*)&K0[((nbo + j) * 8 + r8) * 64 + pcx];
                mma_tf32(sc[j], qa[ks], (const uint32_t*)&bfr);
            }
        }

        // ---- bias (+ mask on final tile) ----
        if (ti < NT - 1) {
            #pragma unroll
            for (int j = 0; j < 4; j++) {
                const int col = (nbo + j) * 8 + 2 * q4;
                #pragma unroll
                for (int jj = 0; jj < 2; jj++) {
                    const uint32_t e = idxc[col + jj];
                    float2 bt = *(const float2*)&bias_sm[(e & 7) * 64 + posr];
                    float2 bh = *(const float2*)&bias_sm[(8 + ((e >> 3) & 15)) * 64 + posr];
                    float2 bw = *(const float2*)&bias_sm[(22 + (e >> 7)) * 64 + posr];
                    sc[j][jj]     += bt.x + bh.x + bw.x;
                    sc[j][jj + 2] += bt.y + bh.y + bw.y;
                }
            }
        } else {
            #pragma unroll
            for (int j = 0; j < 4; j++) {
                const int col = (nbo + j) * 8 + 2 * q4;
                #pragma unroll
                for (int jj = 0; jj < 2; jj++) {
                    if (kb + col + jj < SEQ) {
                        const uint32_t e = idxc[col + jj];
                        float2 bt = *(const float2*)&bias_sm[(e & 7) * 64 + posr];
                        float2 bh = *(const float2*)&bias_sm[(8 + ((e >> 3) & 15)) * 64 + posr];
                        float2 bw = *(const float2*)&bias_sm[(22 + (e >> 7)) * 64 + posr];
                        sc[j][jj]     += bt.x + bh.x + bw.x;
                        sc[j][jj + 2] += bt.y + bh.y + bw.y;
                    } else {
                        sc[j][jj] = -1e30f;
                        sc[j][jj + 2] = -1e30f;
                    }
                }
            }
        }

        // ---- p = 2^s, accumulate partial row sums ----
        #pragma unroll
        for (int j = 0; j < 4; j++) {
            sc[j][0] = ex2(sc[j][0]);
            sc[j][1] = ex2(sc[j][1]);
            sc[j][2] = ex2(sc[j][2]);
            sc[j][3] = ex2(sc[j][3]);
            l0 += sc[j][0] + sc[j][1];
            l1 += sc[j][2] + sc[j][3];
        }

        // ---- O += P V over this group's 32 k values ----
        #pragma unroll
        for (int kc = 0; kc < 4; kc++) {
            uint32_t pa[4];
            pa[0] = f2tf32(sc[kc][0]);
            pa[1] = f2tf32(sc[kc][2]);
            pa[2] = f2tf32(sc[kc][1]);
            pa[3] = f2tf32(sc[kc][3]);
            const uint32_t pkx = ((uint32_t)((nbo + kc) * 8 + 2 * q4)) ^ xv;
            #pragma unroll
            for (int nb = 0; nb < 8; nb++) {
                uint2 bfr = *(const uint2*)&V0[(nb * 8 + r8) * 64 + pkx];
                mma_tf32(accO[nb], pa, (const uint32_t*)&bfr);
            }
        }
    }

    // ---- merge the two K-groups ----
    l0 += __shfl_xor_sync(0xffffffffu, l0, 1);
    l0 += __shfl_xor_sync(0xffffffffu, l0, 2);
    l1 += __shfl_xor_sync(0xffffffffu, l1, 1);
    l1 += __shfl_xor_sync(0xffffffffu, l1, 2);

    __syncthreads();   // tiles dead; red/lred writable
    if (grp == 1) {
        #pragma unroll
        for (int nb = 0; nb < 8; nb++) {
            const int c = nb * 8 + 2 * q4;
            *(float2*)&red[r0 * RED_PITCH + c]       = make_float2(accO[nb][0], accO[nb][1]);
            *(float2*)&red[(r0 + 8) * RED_PITCH + c] = make_float2(accO[nb][2], accO[nb][3]);
        }
        if (q4 == 0) { lred[r0] = l0; lred[r0 + 8] = l1; }
    }
    __syncthreads();
    if (grp == 0) {
        l0 += lred[r0];
        l1 += lred[r0 + 8];
        const float inv0 = 1.f / l0;
        const float inv1 = 1.f / l1;
        const int gq0 = qbase + r0;
        const int gq1 = gq0 + 8;
        #pragma unroll
        for (int nb = 0; nb < 8; nb++) {
            const int c = nb * 8 + 2 * q4;
            float2 p0 = *(const float2*)&red[r0 * RED_PITCH + c];
            float2 p1 = *(const float2*)&red[(r0 + 8) * RED_PITCH + c];
            const int col0 = n * HD + c;
            if (gq0 < SEQ) {
                float2 o0 = make_float2(
                    __uint_as_float(f2tf32((accO[nb][0] + p0.x) * inv0)),
                    __uint_as_float(f2tf32((accO[nb][1] + p0.y) * inv0)));
                *(float2*)(out + ((size_t)b * SEQ + gq0) * DIM + col0) = o0;
            }
            if (gq1 < SEQ) {
                float2 o1 = make_float2(
                    __uint_as_float(f2tf32((accO[nb][2] + p1.x) * inv1)),
                    __uint_as_float(f2tf32((accO[nb][3] + p1.y) * inv1)));
                *(float2*)(out + ((size_t)b * SEQ + gq1) * DIM + col0) = o1;
            }
        }
    }
}

// ---------------- launch ------------------------------------------------------
extern "C" void kernel_launch(void* const* d_in, const int* in_sizes, int n_in,
                              void* d_out, int out_size)
{
    (void)in_sizes; (void)n_in; (void)out_size;
    const float* q   = (const float*)d_in[0];
    const float* k   = (const float*)d_in[1];
    const float* Wq  = (const float*)d_in[2];
    const float* bq  = (const float*)d_in[3];
    const float* Wk  = (const float*)d_in[4];
    const float* bk  = (const float*)d_in[5];
    const float* Wv  = (const float*)d_in[6];
    const float* bv  = (const float*)d_in[7];
    const float* Wo  = (const float*)d_in[8];
    const float* bo  = (const float*)d_in[9];
    const float* rpt = (const float*)d_in[10];
    const float* rph = (const float*)d_in[11];
    const float* rpw = (const float*)d_in[12];
    float* out = (float*)d_out;

    float *p_qh, *p_kh, *p_vt, *p_attn;
    float *p_wq, *p_wk, *p_wv, *p_wo, *p_qr, *p_kr;
    cudaGetSymbolAddress((void**)&p_qh,   g_qh);
    cudaGetSymbolAddress((void**)&p_kh,   g_kh);
    cudaGetSymbolAddress((void**)&p_vt,   g_vt);
    cudaGetSymbolAddress((void**)&p_attn, g_attn);
    cudaGetSymbolAddress((void**)&p_wq,   g_wq);
    cudaGetSymbolAddress((void**)&p_wk,   g_wk);
    cudaGetSymbolAddress((void**)&p_wv,   g_wv);
    cudaGetSymbolAddress((void**)&p_wo,   g_wo);
    cudaGetSymbolAddress((void**)&p_qr,   g_qr);
    cudaGetSymbolAddress((void**)&p_kr,   g_kr);

    static int smem_set = 0;
    if (!smem_set) {
        cudaFuncSetAttribute(gemm_qkv,
                             cudaFuncAttributeMaxDynamicSharedMemorySize, GEMM_SMEM);
        cudaFuncSetAttribute(gemm_o,
                             cudaFuncAttributeMaxDynamicSharedMemorySize, GEMM_SMEM);
        cudaFuncSetAttribute(attn_mma,
                             cudaFuncAttributeMaxDynamicSharedMemorySize, ATTN_SMEM);
        smem_set = 1;
    }

    round_all<<<PRE_BLOCKS, 256>>>(Wq, Wk, Wv, Wo, q, k,
                                   p_wq, p_wk, p_wv, p_wo, p_qr, p_kr);

    dim3 qkvGrid(DIM / 128, (MROWS + 127) / 128, 3);   // 6 x 25 x 3
    gemm_qkv<<<qkvGrid, 256, GEMM_SMEM>>>(p_qr, p_kr, p_wq, bq, p_wk, bk, p_wv, bv,
                                          p_qh, p_kh, p_vt);

    dim3 attnGrid((SEQ + 63) / 64, NH, BATCH);         // 25 x 12 x 2
    attn_mma<<<attnGrid, 256, ATTN_SMEM>>>(p_qh, p_kh, p_vt, rpt, rph, rpw, p_attn);

    dim3 oGrid(DIM / 128, (MROWS + 127) / 128);        // 6 x 25
    gemm_o<<<oGrid, 256, GEMM_SMEM>>>(p_attn, p_wo, bo, out);
}